// round 15
// baseline (speedup 1.0000x reference)
#include <cuda_runtime.h>
#include <cuda_fp16.h>
#include <math.h>
#include <stdint.h>

#define NTOK 8192
#define DIM  1024
#define NEXP 32
#define HID  128
#define TK   4
#define SHID 512
#define NROWS (NTOK*TK)
#define CAP  32768

// ---------------- scratch (device globals; no allocations) ----------------
__device__ __align__(16) int   g_cursor[NEXP];
__device__ __align__(16) int   g_bucket_src[(size_t)NEXP * CAP];
__device__ __align__(16) float g_bucket_sc [(size_t)NEXP * CAP];
__device__ __align__(16) __half g_xh[(size_t)NTOK * DIM];
__device__ __align__(16) __half g_gwh[(size_t)NEXP * HID * DIM];
__device__ __align__(16) __half g_uwh[(size_t)NEXP * HID * DIM];
__device__ __align__(16) __half g_dwh[(size_t)NEXP * DIM * HID];
__device__ __align__(16) __half g_sgwh[(size_t)SHID * DIM];
__device__ __align__(16) __half g_suwh[(size_t)SHID * DIM];
__device__ __align__(16) __half g_sdwh[(size_t)DIM * SHID];
__device__ __align__(16) __half g_sHh[(size_t)NTOK * SHID];
__device__ __align__(16) __half g_Y[(size_t)NROWS * DIM];

// ---------------- helpers ---------------------------------------------------
__device__ __forceinline__ uint32_t s2u(const void* p) {
    uint32_t r;
    asm("{.reg .u64 t; cvta.to.shared.u64 t, %1; cvt.u32.u64 %0, t;}" : "=r"(r) : "l"(p));
    return r;
}
__device__ __forceinline__ uint32_t swz(uint32_t b) { return b ^ ((b >> 3) & 0x70); }

__device__ __forceinline__ void cpa16h(uint32_t daddr, const __half* src, bool pred) {
    int sz = pred ? 16 : 0;
    asm volatile("cp.async.cg.shared.global [%0], [%1], 16, %2;\n"
                 :: "r"(daddr), "l"(src), "r"(sz));
}
__device__ __forceinline__ void cp_commit() {
    asm volatile("cp.async.commit_group;\n" ::);
}
template<int N> __device__ __forceinline__ void cp_wait() {
    asm volatile("cp.async.wait_group %0;\n" :: "n"(N));
}
__device__ __forceinline__ void sts32(uint32_t addr, uint32_t v) {
    asm volatile("st.shared.b32 [%0], %1;" :: "r"(addr), "r"(v) : "memory");
}
__device__ __forceinline__ void mma16(float* c, const uint32_t* a, const uint32_t* b) {
    asm volatile(
        "mma.sync.aligned.m16n8k16.row.col.f32.f16.f16.f32 "
        "{%0,%1,%2,%3}, {%4,%5,%6,%7}, {%8,%9}, {%0,%1,%2,%3};"
        : "+f"(c[0]), "+f"(c[1]), "+f"(c[2]), "+f"(c[3])
        : "r"(a[0]), "r"(a[1]), "r"(a[2]), "r"(a[3]), "r"(b[0]), "r"(b[1]));
}
__device__ __forceinline__ float silu_mul(float g, float u) {
    return g / (1.f + __expf(-g)) * u;
}
__device__ __forceinline__ void ldsm4(uint32_t* r, uint32_t addr) {
    asm volatile("ldmatrix.sync.aligned.m8n8.x4.shared.b16 {%0,%1,%2,%3}, [%4];"
        : "=r"(r[0]), "=r"(r[1]), "=r"(r[2]), "=r"(r[3]) : "r"(addr));
}

#define TILE_BYTES 16384u
#define SMEM_GU3  (3 * 3 * TILE_BYTES)      // 144 KB (gu fused)
#define SMEM_FIN  (3 * 2 * TILE_BYTES)      // 96 KB (final 128x128, 3-stage)
#define SMEM_RTR  (32 * DIM * 4)            // 128 KB (router x staging)

// single-B k64 compute, warp tile 32x64
__device__ __forceinline__ void compute_k64h(
    uint32_t sAt, uint32_t sBt, int wm, int wn, int lane, float acc[2][8][4]) {
    int ar = lane & 15, ac = lane >> 4;
    int br = (lane & 7) + ((lane >> 4) & 1) * 8;
    int bc = (lane >> 3) & 1;
#pragma unroll
    for (int ks = 0; ks < 4; ks++) {
        uint32_t af[2][4];
#pragma unroll
        for (int mt = 0; mt < 2; mt++)
            ldsm4(af[mt], sAt + swz((uint32_t)((wm + mt * 16 + ar) * 128 + (ks * 2 + ac) * 16)));
        uint32_t bf[8][2];
#pragma unroll
        for (int j = 0; j < 4; j++) {
            uint32_t r[4];
            ldsm4(r, sBt + swz((uint32_t)((wn + 16 * j + br) * 128 + (ks * 2 + bc) * 16)));
            bf[2*j][0] = r[0]; bf[2*j][1] = r[1]; bf[2*j+1][0] = r[2]; bf[2*j+1][1] = r[3];
        }
#pragma unroll
        for (int mt = 0; mt < 2; mt++)
#pragma unroll
            for (int nt = 0; nt < 8; nt++) mma16(acc[mt][nt], af[mt], bf[nt]);
    }
}

// single-B k64 compute, warp tile 32x32 (down phase)
__device__ __forceinline__ void compute_k64h_32(
    uint32_t sAt, uint32_t sBt, int wm, int wn, int lane, float acc[2][4][4]) {
    int ar = lane & 15, ac = lane >> 4;
    int br = (lane & 7) + ((lane >> 4) & 1) * 8;
    int bc = (lane >> 3) & 1;
#pragma unroll
    for (int ks = 0; ks < 4; ks++) {
        uint32_t af[2][4];
#pragma unroll
        for (int mt = 0; mt < 2; mt++)
            ldsm4(af[mt], sAt + swz((uint32_t)((wm + mt * 16 + ar) * 128 + (ks * 2 + ac) * 16)));
        uint32_t bf[4][2];
#pragma unroll
        for (int j = 0; j < 2; j++) {
            uint32_t r[4];
            ldsm4(r, sBt + swz((uint32_t)((wn + 16 * j + br) * 128 + (ks * 2 + bc) * 16)));
            bf[2*j][0] = r[0]; bf[2*j][1] = r[1]; bf[2*j+1][0] = r[2]; bf[2*j+1][1] = r[3];
        }
#pragma unroll
        for (int mt = 0; mt < 2; mt++)
#pragma unroll
            for (int nt = 0; nt < 4; nt++) mma16(acc[mt][nt], af[mt], bf[nt]);
    }
}

// fused gate+up compute, 512 threads: warp tile 32x32 per output matrix
__device__ __forceinline__ void compute_k64h_gu512(
    uint32_t sAt, uint32_t sBg, uint32_t sBu, int wm, int wn, int lane,
    float accg[2][4][4], float accu[2][4][4]) {
    int ar = lane & 15, ac = lane >> 4;
    int br = (lane & 7) + ((lane >> 4) & 1) * 8;
    int bc = (lane >> 3) & 1;
#pragma unroll
    for (int ks = 0; ks < 4; ks++) {
        uint32_t af[2][4];
#pragma unroll
        for (int mt = 0; mt < 2; mt++)
            ldsm4(af[mt], sAt + swz((uint32_t)((wm + mt * 16 + ar) * 128 + (ks * 2 + ac) * 16)));
        uint32_t bf[4][2];
#pragma unroll
        for (int j = 0; j < 2; j++) {
            uint32_t r[4];
            ldsm4(r, sBg + swz((uint32_t)((wn + 16 * j + br) * 128 + (ks * 2 + bc) * 16)));
            bf[2*j][0] = r[0]; bf[2*j][1] = r[1]; bf[2*j+1][0] = r[2]; bf[2*j+1][1] = r[3];
        }
#pragma unroll
        for (int mt = 0; mt < 2; mt++)
#pragma unroll
            for (int nt = 0; nt < 4; nt++) mma16(accg[mt][nt], af[mt], bf[nt]);
#pragma unroll
        for (int j = 0; j < 2; j++) {
            uint32_t r[4];
            ldsm4(r, sBu + swz((uint32_t)((wn + 16 * j + br) * 128 + (ks * 2 + bc) * 16)));
            bf[2*j][0] = r[0]; bf[2*j][1] = r[1]; bf[2*j+1][0] = r[2]; bf[2*j+1][1] = r[3];
        }
#pragma unroll
        for (int mt = 0; mt < 2; mt++)
#pragma unroll
            for (int nt = 0; nt < 4; nt++) mma16(accu[mt][nt], af[mt], bf[nt]);
    }
}

// ---------------- K0: convW (6 weight arrays, 32 floats/thread) + init --------
#define NG8  ((unsigned)(NEXP * HID * DIM / 8))
#define NS8  ((unsigned)(SHID * DIM / 8))
#define W1 (NG8)
#define W2 (2u * NG8)
#define W3 (3u * NG8)
#define W4 (W3 + NS8)
#define W5 (W4 + NS8)
#define W6 (W5 + NS8)

__global__ __launch_bounds__(256) void convw_kernel(
    const float* __restrict__ gw, const float* __restrict__ uw,
    const float* __restrict__ dw, const float* __restrict__ sgw,
    const float* __restrict__ suw, const float* __restrict__ sdw) {
    if (blockIdx.x == 0 && threadIdx.x < NEXP) g_cursor[threadIdx.x] = 0;
    unsigned q = (blockIdx.x * 256 + threadIdx.x) * 4;
    if (q >= W6) return;
    const float* src; __half* dst; unsigned base;
    if      (q < W1) { src = gw;  dst = g_gwh;  base = 0; }
    else if (q < W2) { src = uw;  dst = g_uwh;  base = W1; }
    else if (q < W3) { src = dw;  dst = g_dwh;  base = W2; }
    else if (q < W4) { src = sgw; dst = g_sgwh; base = W3; }
    else if (q < W5) { src = suw; dst = g_suwh; base = W4; }
    else             { src = sdw; dst = g_sdwh; base = W5; }
    size_t e = (size_t)(q - base) * 8;
    const float4* s = (const float4*)(src + e);
    float4 v[8];
#pragma unroll
    for (int i = 0; i < 8; i++) v[i] = s[i];
#pragma unroll
    for (int i = 0; i < 4; i++) {
        __half2 h[4];
        h[0] = __floats2half2_rn(v[2*i].x, v[2*i].y);
        h[1] = __floats2half2_rn(v[2*i].z, v[2*i].w);
        h[2] = __floats2half2_rn(v[2*i+1].x, v[2*i+1].y);
        h[3] = __floats2half2_rn(v[2*i+1].z, v[2*i+1].w);
        *(uint4*)(dst + e + i * 8) = *(uint4*)h;
    }
}

// ---------------- K1: router (32 tokens/block) + top4 + scatter + x->fp16 -----
__global__ __launch_bounds__(256) void router_scatter_kernel(
    const float* __restrict__ x, const float* __restrict__ rw,
    const float* __restrict__ rb) {
    extern __shared__ float xs[];   // 32 x 1024 floats
    int tok0 = blockIdx.x * 32;
    int t = threadIdx.x;
#pragma unroll
    for (int i = 0; i < 32; i++) {
        int s = t + i * 256;               // 8192 float4 slots
        int r = s >> 8; int q = s & 255;
        *(float4*)(xs + r * DIM + q * 4) =
            *(const float4*)(x + (size_t)(tok0 + r) * DIM + q * 4);
    }
    __syncthreads();
    // emit fp16 x (32 tokens x 1024) — 128 floats per thread
#pragma unroll
    for (int i = 0; i < 16; i++) {
        int c = (t + i * 256) * 8;
        const float4* sv = (const float4*)(xs + c);
        float4 a = sv[0], b = sv[1];
        __half2 h[4];
        h[0] = __floats2half2_rn(a.x, a.y); h[1] = __floats2half2_rn(a.z, a.w);
        h[2] = __floats2half2_rn(b.x, b.y); h[3] = __floats2half2_rn(b.z, b.w);
        *(uint4*)(g_xh + (size_t)tok0 * DIM + c) = *(uint4*)h;
    }
    int wrp = t >> 5, lane = t & 31;
    const float4* wv = (const float4*)(rw + (size_t)lane * DIM);
#pragma unroll
    for (int i = 0; i < 4; i++) {
        int tok = tok0 + wrp * 4 + i;
        float acc = rb[lane];
        const float4* xv = (const float4*)(xs + (wrp * 4 + i) * DIM);
#pragma unroll 4
        for (int q = 0; q < DIM / 4; q++) {
            float4 a = xv[q], b = wv[q];
            acc = fmaf(a.x, b.x, acc); acc = fmaf(a.y, b.y, acc);
            acc = fmaf(a.z, b.z, acc); acc = fmaf(a.w, b.w, acc);
        }
        float m = acc;
#pragma unroll
        for (int o = 16; o; o >>= 1) m = fmaxf(m, __shfl_xor_sync(~0u, m, o));
        float p = __expf(acc - m);
        float s = p;
#pragma unroll
        for (int o = 16; o; o >>= 1) s += __shfl_xor_sync(~0u, s, o);
        float sc = p / s;
        float cs[TK]; int ci[TK];
        float cur = sc;
#pragma unroll
        for (int k = 0; k < TK; k++) {
            float v = cur; int vi = lane;
#pragma unroll
            for (int o = 16; o; o >>= 1) {
                float ov = __shfl_xor_sync(~0u, v, o);
                int   oi = __shfl_xor_sync(~0u, vi, o);
                if (ov > v || (ov == v && oi < vi)) { v = ov; vi = oi; }
            }
            cs[k] = v; ci[k] = vi;
            if (lane == vi) cur = -1.f;
        }
        float inv = 1.f / fmaxf(cs[0] + cs[1] + cs[2] + cs[3], 1e-12f);
        if (lane < TK) {
            int e = ci[lane];
            int pos = atomicAdd(&g_cursor[e], 1);
            g_bucket_src[(size_t)e * CAP + pos] = tok * TK + lane;
            g_bucket_sc [(size_t)e * CAP + pos] = cs[lane] * inv;
        }
    }
}

// ---------------- K2: FUSED gate+up+SiLU(+down for routed) --------------------
__global__ __launch_bounds__(512) void gu_all_kernel(
    const __half* __restrict__ gwp, const __half* __restrict__ uwp,
    const __half* __restrict__ sgwp, const __half* __restrict__ suwp,
    const __half* __restrict__ dwp) {
    int by = blockIdx.y;
    int tile0 = blockIdx.x * 128;
    int t = threadIdx.x;
    extern __shared__ __half smh[];
    uint32_t sA = s2u(smh), sBg = sA + 3 * TILE_BYTES, sBu = sA + 6 * TILE_BYTES;
    __shared__ int srcs[128];
    __shared__ float scs[128];

    bool routed = by < NEXP;
    int cnt;
    const __half *Wg, *Wu;
    if (routed) {
        cnt = g_cursor[by];
        if (tile0 >= cnt) return;
        size_t off = (size_t)by * CAP;
        Wg = gwp + (size_t)by * HID * DIM;
        Wu = uwp + (size_t)by * HID * DIM;
        if (t < 128) {
            int m = tile0 + t;
            bool v = m < cnt;
            srcs[t] = v ? g_bucket_src[off + m] : -1;
            scs[t]  = v ? g_bucket_sc[off + m] : 0.f;
        }
    } else {
        int nb = (by - NEXP) * 128;
        cnt = NTOK;
        Wg = sgwp + (size_t)nb * DIM;
        Wu = suwp + (size_t)nb * DIM;
        if (t < 128) srcs[t] = tile0 + t;
    }
    __syncthreads();

    int shift = routed ? 2 : 0;
    int rw_[2], cw[2]; const __half* aP[2]; const __half* gP[2]; const __half* uP[2]; bool av[2];
#pragma unroll
    for (int i = 0; i < 2; i++) {
        int c = t + i * 512; rw_[i] = c >> 3; cw[i] = c & 7;
        int s0 = srcs[rw_[i]];
        av[i] = s0 >= 0;
        int tok = (av[i] ? s0 : 0) >> shift;
        aP[i] = g_xh + (size_t)tok * DIM + cw[i] * 8;
        gP[i] = Wg + (size_t)rw_[i] * DIM + cw[i] * 8;
        uP[i] = Wu + (size_t)rw_[i] * DIM + cw[i] * 8;
    }
    int lane = t & 31, wid = t >> 5;
    int wm = (wid & 3) * 32, wn = (wid >> 2) * 32, g = lane >> 2, tig = lane & 3;
    float accg[2][4][4] = {}, accu[2][4][4] = {};

#define GU_ISSUE(st, kb)                                                        \
    {                                                                           \
        uint32_t so = (uint32_t)(st) * TILE_BYTES;                              \
        _Pragma("unroll")                                                       \
        for (int i = 0; i < 2; i++) {                                           \
            uint32_t o = swz((uint32_t)(rw_[i] * 128 + cw[i] * 16));            \
            cpa16h(sA + so + o, aP[i] + (kb), av[i]);                           \
            cpa16h(sBg + so + o, gP[i] + (kb), true);                           \
            cpa16h(sBu + so + o, uP[i] + (kb), true);                           \
        }                                                                       \
        cp_commit();                                                            \
    }

    const int NIT = DIM / 64;     // 16
    GU_ISSUE(0, 0) GU_ISSUE(1, 64)
    for (int it = 0; it < NIT; it++) {
        if (it + 1 < NIT) cp_wait<1>(); else cp_wait<0>();
        __syncthreads();
        int st = it % 3;
        compute_k64h_gu512(sA + st * TILE_BYTES, sBg + st * TILE_BYTES,
                           sBu + st * TILE_BYTES, wm, wn, lane, accg, accu);
        int nx = it + 2;
        if (nx < NIT) GU_ISSUE(nx % 3, nx * 64)
    }
#undef GU_ISSUE

    if (!routed) {
        int nb = (by - NEXP) * 128;
        __half* outp = g_sHh + nb;
#pragma unroll
        for (int mt = 0; mt < 2; mt++) {
            int rA = tile0 + wm + mt * 16 + g;
#pragma unroll
            for (int nt = 0; nt < 4; nt++) {
                int col = wn + nt * 8 + 2 * tig;
                __half2 h0 = __floats2half2_rn(
                    silu_mul(accg[mt][nt][0], accu[mt][nt][0]),
                    silu_mul(accg[mt][nt][1], accu[mt][nt][1]));
                *(__half2*)(outp + (size_t)rA * SHID + col) = h0;
                __half2 h1 = __floats2half2_rn(
                    silu_mul(accg[mt][nt][2], accu[mt][nt][2]),
                    silu_mul(accg[mt][nt][3], accu[mt][nt][3]));
                *(__half2*)(outp + (size_t)(rA + 8) * SHID + col) = h1;
            }
        }
        return;
    }

    // ---- routed: in-CTA down GEMM ----
    __syncthreads();

    const __half* W = dwp + (size_t)by * DIM * HID;
#define WD_ISSUE(j)                                                             \
    {                                                                           \
        int nbv = (j) >> 1, kv = (j) & 1;                                       \
        uint32_t slot = ((uint32_t)(j) % 3) * TILE_BYTES;                       \
        _Pragma("unroll")                                                       \
        for (int i = 0; i < 2; i++) {                                           \
            uint32_t o = swz((uint32_t)(rw_[i] * 128 + cw[i] * 16));            \
            cpa16h(sBg + slot + o,                                              \
                   W + (size_t)(nbv * 128 + rw_[i]) * HID + kv * 64 + cw[i] * 8, true); \
        }                                                                       \
        cp_commit();                                                            \
    }
    WD_ISSUE(0) WD_ISSUE(1)

#pragma unroll
    for (int mt = 0; mt < 2; mt++) {
        int rL = wm + mt * 16 + g;
#pragma unroll
        for (int nt = 0; nt < 4; nt++) {
            int col = wn + nt * 8 + 2 * tig;
            uint32_t chunk = (uint32_t)(col >> 6);
            uint32_t colb = (uint32_t)((col & 63) * 2);
            __half2 h0 = __floats2half2_rn(
                silu_mul(accg[mt][nt][0], accu[mt][nt][0]),
                silu_mul(accg[mt][nt][1], accu[mt][nt][1]));
            sts32(sA + chunk * TILE_BYTES +
                  (((uint32_t)rL * 128 + colb) ^ (((uint32_t)rL & 7) << 4)),
                  *(uint32_t*)&h0);
            int rH = rL + 8;
            __half2 h1 = __floats2half2_rn(
                silu_mul(accg[mt][nt][2], accu[mt][nt][2]),
                silu_mul(accg[mt][nt][3], accu[mt][nt][3]));
            sts32(sA + chunk * TILE_BYTES +
                  (((uint32_t)rH * 128 + colb) ^ (((uint32_t)rH & 7) << 4)),
                  *(uint32_t*)&h1);
        }
    }
    __syncthreads();

    float acc[2][4][4] = {};
    for (int j = 0; j < 16; j++) {
        if (j + 1 < 16) cp_wait<1>(); else cp_wait<0>();
        __syncthreads();
        compute_k64h_32(sA + (j & 1) * TILE_BYTES, sBg + (j % 3) * TILE_BYTES,
                        wm, wn, lane, acc);
        int nx = j + 2;
        if (nx < 16) WD_ISSUE(nx)
        if (j & 1) {
            int nb = j >> 1;
#pragma unroll
            for (int mt = 0; mt < 2; mt++) {
                int rL = wm + mt * 16 + g;
                int s0 = srcs[rL], s1 = srcs[rL + 8];
#pragma unroll
                for (int nt = 0; nt < 4; nt++) {
                    int col = nb * 128 + wn + nt * 8 + 2 * tig;
                    if (s0 >= 0) {
                        float s = scs[rL];
                        *(__half2*)(g_Y + (size_t)s0 * DIM + col) =
                            __floats2half2_rn(acc[mt][nt][0] * s, acc[mt][nt][1] * s);
                    }
                    if (s1 >= 0) {
                        float s = scs[rL + 8];
                        *(__half2*)(g_Y + (size_t)s1 * DIM + col) =
                            __floats2half2_rn(acc[mt][nt][2] * s, acc[mt][nt][3] * s);
                    }
                }
            }
#pragma unroll
            for (int mt = 0; mt < 2; mt++)
#pragma unroll
                for (int nt = 0; nt < 4; nt++)
#pragma unroll
                    for (int v = 0; v < 4; v++) acc[mt][nt][v] = 0.f;
        }
    }
#undef WD_ISSUE
}

// ---------------- K3: final GEMM 128x128 (256 thr, 2 CTA/SM) + Y gather --------
__global__ __launch_bounds__(256, 2) void final_kernel(
    const __half* __restrict__ sdwp, float* __restrict__ out) {
    int tile0 = blockIdx.x * 128;
    int nb = blockIdx.y * 128;
    extern __shared__ __half smh[];
    uint32_t sA = s2u(smh), sB = sA + 3 * TILE_BYTES;
    int t = threadIdx.x;

    int rw_[4], cw[4]; const __half* aP[4]; const __half* bP[4];
#pragma unroll
    for (int i = 0; i < 4; i++) {
        int c = t + i * 256; rw_[i] = c >> 3; cw[i] = c & 7;
        aP[i] = g_sHh + (size_t)(tile0 + rw_[i]) * SHID + cw[i] * 8;
        bP[i] = sdwp + (size_t)(nb + rw_[i]) * SHID + cw[i] * 8;
    }
    int lane = t & 31, wid = t >> 5;
    int wm = (wid & 3) * 32, wn = (wid >> 2) * 64, g = lane >> 2, tig = lane & 3;
    float acc[2][8][4] = {};

#define AB_ISSUE(st, kb)                                                        \
    {                                                                           \
        uint32_t so = (uint32_t)(st) * TILE_BYTES;                              \
        _Pragma("unroll")                                                       \
        for (int i = 0; i < 4; i++) {                                           \
            uint32_t o = swz((uint32_t)(rw_[i] * 128 + cw[i] * 16));            \
            cpa16h(sA + so + o, aP[i] + (kb), true);                            \
            cpa16h(sB + so + o, bP[i] + (kb), true);                            \
        }                                                                       \
        cp_commit();                                                            \
    }

    {
        const int NIT = SHID / 64;   // 8
        AB_ISSUE(0, 0) AB_ISSUE(1, 64)
        for (int it = 0; it < NIT; it++) {
            if (it + 1 < NIT) cp_wait<1>(); else cp_wait<0>();
            __syncthreads();
            int st = it % 3;
            compute_k64h(sA + st * TILE_BYTES, sB + st * TILE_BYTES, wm, wn, lane, acc);
            int nx = it + 2;
            if (nx < NIT) AB_ISSUE(nx % 3, nx * 64)
        }
    }
#undef AB_ISSUE

#pragma unroll
    for (int mt = 0; mt < 2; mt++) {
        int r0 = tile0 + wm + mt * 16 + g;
        const __half* ya = g_Y + (size_t)r0 * TK * DIM;
        const __half* yb = g_Y + (size_t)(r0 + 8) * TK * DIM;
#pragma unroll
        for (int nt = 0; nt < 8; nt++) {
            int col = nb + wn + nt * 8 + 2 * tig;
            float2 f0 = __half22float2(*(const __half2*)(ya + col));
            float2 f1 = __half22float2(*(const __half2*)(ya + DIM + col));
            float2 f2 = __half22float2(*(const __half2*)(ya + 2 * DIM + col));
            float2 f3 = __half22float2(*(const __half2*)(ya + 3 * DIM + col));
            float2 ra;
            ra.x = acc[mt][nt][0] + f0.x + f1.x + f2.x + f3.x;
            ra.y = acc[mt][nt][1] + f0.y + f1.y + f2.y + f3.y;
            *(float2*)(out + (size_t)r0 * DIM + col) = ra;
            float2 z0 = __half22float2(*(const __half2*)(yb + col));
            float2 z1 = __half22float2(*(const __half2*)(yb + DIM + col));
            float2 z2 = __half22float2(*(const __half2*)(yb + 2 * DIM + col));
            float2 z3 = __half22float2(*(const __half2*)(yb + 3 * DIM + col));
            float2 rb;
            rb.x = acc[mt][nt][2] + z0.x + z1.x + z2.x + z3.x;
            rb.y = acc[mt][nt][3] + z0.y + z1.y + z2.y + z3.y;
            *(float2*)(out + (size_t)(r0 + 8) * DIM + col) = rb;
        }
    }
}

// ---------------- launch ---------------------------------------------------------
extern "C" void kernel_launch(void* const* d_in, const int* in_sizes, int n_in,
                              void* d_out, int out_size) {
    const float* x   = (const float*)d_in[0];
    const float* rw  = (const float*)d_in[1];
    const float* rb  = (const float*)d_in[2];
    const float* gw  = (const float*)d_in[3];
    const float* uw  = (const float*)d_in[4];
    const float* dw  = (const float*)d_in[5];
    const float* sgw = (const float*)d_in[6];
    const float* suw = (const float*)d_in[7];
    const float* sdw = (const float*)d_in[8];
    float* out = (float*)d_out;

    static __half *p_gwh = nullptr, *p_uwh, *p_dwh, *p_sgwh, *p_suwh, *p_sdwh;
    if (!p_gwh) {
        cudaGetSymbolAddress((void**)&p_gwh,  g_gwh);
        cudaGetSymbolAddress((void**)&p_uwh,  g_uwh);
        cudaGetSymbolAddress((void**)&p_dwh,  g_dwh);
        cudaGetSymbolAddress((void**)&p_sgwh, g_sgwh);
        cudaGetSymbolAddress((void**)&p_suwh, g_suwh);
        cudaGetSymbolAddress((void**)&p_sdwh, g_sdwh);
    }

    cudaFuncSetAttribute(router_scatter_kernel, cudaFuncAttributeMaxDynamicSharedMemorySize, SMEM_RTR);
    cudaFuncSetAttribute(gu_all_kernel, cudaFuncAttributeMaxDynamicSharedMemorySize, SMEM_GU3);
    cudaFuncSetAttribute(final_kernel,  cudaFuncAttributeMaxDynamicSharedMemorySize, SMEM_FIN);

    convw_kernel<<<(W6 / 4 + 255) / 256, 256>>>(gw, uw, dw, sgw, suw, sdw);          // 0
    router_scatter_kernel<<<NTOK / 32, 256, SMEM_RTR>>>(x, rw, rb);                  // 1
    gu_all_kernel<<<dim3(64, NEXP + 4), 512, SMEM_GU3>>>(p_gwh, p_uwh, p_sgwh, p_suwh, p_dwh); // 2
    final_kernel<<<dim3(64, 8), 256, SMEM_FIN>>>(p_sdwh, out);                       // 3
}

// round 16
// speedup vs baseline: 1.0933x; 1.0933x over previous
#include <cuda_runtime.h>
#include <cuda_fp16.h>
#include <math.h>
#include <stdint.h>

#define NTOK 8192
#define DIM  1024
#define NEXP 32
#define HID  128
#define TK   4
#define SHID 512
#define NROWS (NTOK*TK)
#define CAP  32768

// ---------------- scratch (device globals; no allocations) ----------------
__device__ __align__(16) int   g_cursor[NEXP];
__device__ __align__(16) int   g_bucket_src[(size_t)NEXP * CAP];
__device__ __align__(16) float g_bucket_sc [(size_t)NEXP * CAP];
__device__ __align__(16) __half g_xh[(size_t)NTOK * DIM];
__device__ __align__(16) __half g_gwh[(size_t)NEXP * HID * DIM];
__device__ __align__(16) __half g_uwh[(size_t)NEXP * HID * DIM];
__device__ __align__(16) __half g_dwh[(size_t)NEXP * DIM * HID];
__device__ __align__(16) __half g_sgwh[(size_t)SHID * DIM];
__device__ __align__(16) __half g_suwh[(size_t)SHID * DIM];
__device__ __align__(16) __half g_sdwh[(size_t)DIM * SHID];
__device__ __align__(16) __half g_sHh[(size_t)NTOK * SHID];
__device__ __align__(16) __half g_Y[(size_t)NROWS * DIM];

// ---------------- helpers ---------------------------------------------------
__device__ __forceinline__ uint32_t s2u(const void* p) {
    uint32_t r;
    asm("{.reg .u64 t; cvta.to.shared.u64 t, %1; cvt.u32.u64 %0, t;}" : "=r"(r) : "l"(p));
    return r;
}
__device__ __forceinline__ uint32_t swz(uint32_t b) { return b ^ ((b >> 3) & 0x70); }

__device__ __forceinline__ void cpa16h(uint32_t daddr, const __half* src, bool pred) {
    int sz = pred ? 16 : 0;
    asm volatile("cp.async.cg.shared.global [%0], [%1], 16, %2;\n"
                 :: "r"(daddr), "l"(src), "r"(sz));
}
__device__ __forceinline__ void cp_commit() {
    asm volatile("cp.async.commit_group;\n" ::);
}
template<int N> __device__ __forceinline__ void cp_wait() {
    asm volatile("cp.async.wait_group %0;\n" :: "n"(N));
}
__device__ __forceinline__ void sts32(uint32_t addr, uint32_t v) {
    asm volatile("st.shared.b32 [%0], %1;" :: "r"(addr), "r"(v) : "memory");
}
__device__ __forceinline__ void mma16(float* c, const uint32_t* a, const uint32_t* b) {
    asm volatile(
        "mma.sync.aligned.m16n8k16.row.col.f32.f16.f16.f32 "
        "{%0,%1,%2,%3}, {%4,%5,%6,%7}, {%8,%9}, {%0,%1,%2,%3};"
        : "+f"(c[0]), "+f"(c[1]), "+f"(c[2]), "+f"(c[3])
        : "r"(a[0]), "r"(a[1]), "r"(a[2]), "r"(a[3]), "r"(b[0]), "r"(b[1]));
}
__device__ __forceinline__ float silu_mul(float g, float u) {
    return g / (1.f + __expf(-g)) * u;
}
__device__ __forceinline__ void ldsm4(uint32_t* r, uint32_t addr) {
    asm volatile("ldmatrix.sync.aligned.m8n8.x4.shared.b16 {%0,%1,%2,%3}, [%4];"
        : "=r"(r[0]), "=r"(r[1]), "=r"(r[2]), "=r"(r[3]) : "r"(addr));
}

#define TILE_BYTES 16384u
#define SMEM_GU3  (3 * 3 * TILE_BYTES)
#define SMEM_FIN  (3 * 2 * TILE_BYTES)

// single-B k64 compute, warp tile 32x64
__device__ __forceinline__ void compute_k64h(
    uint32_t sAt, uint32_t sBt, int wm, int wn, int lane, float acc[2][8][4]) {
    int ar = lane & 15, ac = lane >> 4;
    int br = (lane & 7) + ((lane >> 4) & 1) * 8;
    int bc = (lane >> 3) & 1;
#pragma unroll
    for (int ks = 0; ks < 4; ks++) {
        uint32_t af[2][4];
#pragma unroll
        for (int mt = 0; mt < 2; mt++)
            ldsm4(af[mt], sAt + swz((uint32_t)((wm + mt * 16 + ar) * 128 + (ks * 2 + ac) * 16)));
        uint32_t bf[8][2];
#pragma unroll
        for (int j = 0; j < 4; j++) {
            uint32_t r[4];
            ldsm4(r, sBt + swz((uint32_t)((wn + 16 * j + br) * 128 + (ks * 2 + bc) * 16)));
            bf[2*j][0] = r[0]; bf[2*j][1] = r[1]; bf[2*j+1][0] = r[2]; bf[2*j+1][1] = r[3];
        }
#pragma unroll
        for (int mt = 0; mt < 2; mt++)
#pragma unroll
            for (int nt = 0; nt < 8; nt++) mma16(acc[mt][nt], af[mt], bf[nt]);
    }
}

// single-B k64 compute, warp tile 32x32 (down phase)
__device__ __forceinline__ void compute_k64h_32(
    uint32_t sAt, uint32_t sBt, int wm, int wn, int lane, float acc[2][4][4]) {
    int ar = lane & 15, ac = lane >> 4;
    int br = (lane & 7) + ((lane >> 4) & 1) * 8;
    int bc = (lane >> 3) & 1;
#pragma unroll
    for (int ks = 0; ks < 4; ks++) {
        uint32_t af[2][4];
#pragma unroll
        for (int mt = 0; mt < 2; mt++)
            ldsm4(af[mt], sAt + swz((uint32_t)((wm + mt * 16 + ar) * 128 + (ks * 2 + ac) * 16)));
        uint32_t bf[4][2];
#pragma unroll
        for (int j = 0; j < 2; j++) {
            uint32_t r[4];
            ldsm4(r, sBt + swz((uint32_t)((wn + 16 * j + br) * 128 + (ks * 2 + bc) * 16)));
            bf[2*j][0] = r[0]; bf[2*j][1] = r[1]; bf[2*j+1][0] = r[2]; bf[2*j+1][1] = r[3];
        }
#pragma unroll
        for (int mt = 0; mt < 2; mt++)
#pragma unroll
            for (int nt = 0; nt < 4; nt++) mma16(acc[mt][nt], af[mt], bf[nt]);
    }
}

// fused gate+up compute, 512 threads
__device__ __forceinline__ void compute_k64h_gu512(
    uint32_t sAt, uint32_t sBg, uint32_t sBu, int wm, int wn, int lane,
    float accg[2][4][4], float accu[2][4][4]) {
    int ar = lane & 15, ac = lane >> 4;
    int br = (lane & 7) + ((lane >> 4) & 1) * 8;
    int bc = (lane >> 3) & 1;
#pragma unroll
    for (int ks = 0; ks < 4; ks++) {
        uint32_t af[2][4];
#pragma unroll
        for (int mt = 0; mt < 2; mt++)
            ldsm4(af[mt], sAt + swz((uint32_t)((wm + mt * 16 + ar) * 128 + (ks * 2 + ac) * 16)));
        uint32_t bf[4][2];
#pragma unroll
        for (int j = 0; j < 2; j++) {
            uint32_t r[4];
            ldsm4(r, sBg + swz((uint32_t)((wn + 16 * j + br) * 128 + (ks * 2 + bc) * 16)));
            bf[2*j][0] = r[0]; bf[2*j][1] = r[1]; bf[2*j+1][0] = r[2]; bf[2*j+1][1] = r[3];
        }
#pragma unroll
        for (int mt = 0; mt < 2; mt++)
#pragma unroll
            for (int nt = 0; nt < 4; nt++) mma16(accg[mt][nt], af[mt], bf[nt]);
#pragma unroll
        for (int j = 0; j < 2; j++) {
            uint32_t r[4];
            ldsm4(r, sBu + swz((uint32_t)((wn + 16 * j + br) * 128 + (ks * 2 + bc) * 16)));
            bf[2*j][0] = r[0]; bf[2*j][1] = r[1]; bf[2*j+1][0] = r[2]; bf[2*j+1][1] = r[3];
        }
#pragma unroll
        for (int mt = 0; mt < 2; mt++)
#pragma unroll
            for (int nt = 0; nt < 4; nt++) mma16(accu[mt][nt], af[mt], bf[nt]);
    }
}

// ---------------- K0: convW + init -------------------------------------------
#define NG8  ((unsigned)(NEXP * HID * DIM / 8))
#define NS8  ((unsigned)(SHID * DIM / 8))
#define W1 (NG8)
#define W2 (2u * NG8)
#define W3 (3u * NG8)
#define W4 (W3 + NS8)
#define W5 (W4 + NS8)
#define W6 (W5 + NS8)

__global__ __launch_bounds__(256) void convw_kernel(
    const float* __restrict__ gw, const float* __restrict__ uw,
    const float* __restrict__ dw, const float* __restrict__ sgw,
    const float* __restrict__ suw, const float* __restrict__ sdw) {
    if (blockIdx.x == 0 && threadIdx.x < NEXP) g_cursor[threadIdx.x] = 0;
    unsigned q = (blockIdx.x * 256 + threadIdx.x) * 4;
    if (q >= W6) return;
    const float* src; __half* dst; unsigned base;
    if      (q < W1) { src = gw;  dst = g_gwh;  base = 0; }
    else if (q < W2) { src = uw;  dst = g_uwh;  base = W1; }
    else if (q < W3) { src = dw;  dst = g_dwh;  base = W2; }
    else if (q < W4) { src = sgw; dst = g_sgwh; base = W3; }
    else if (q < W5) { src = suw; dst = g_suwh; base = W4; }
    else             { src = sdw; dst = g_sdwh; base = W5; }
    size_t e = (size_t)(q - base) * 8;
    const float4* s = (const float4*)(src + e);
    float4 v[8];
#pragma unroll
    for (int i = 0; i < 8; i++) v[i] = s[i];
#pragma unroll
    for (int i = 0; i < 4; i++) {
        __half2 h[4];
        h[0] = __floats2half2_rn(v[2*i].x, v[2*i].y);
        h[1] = __floats2half2_rn(v[2*i].z, v[2*i].w);
        h[2] = __floats2half2_rn(v[2*i+1].x, v[2*i+1].y);
        h[3] = __floats2half2_rn(v[2*i+1].z, v[2*i+1].w);
        *(uint4*)(dst + e + i * 8) = *(uint4*)h;
    }
}

// ---------------- K1: router (8 tokens/block) + scatter + x->fp16 -------------
__global__ __launch_bounds__(256) void router_scatter_kernel(
    const float* __restrict__ x, const float* __restrict__ rw,
    const float* __restrict__ rb) {
    __shared__ float xs[8 * DIM];
    int tok0 = blockIdx.x * 8;
    int t = threadIdx.x;
#pragma unroll
    for (int i = 0; i < 8; i++) {
        int s = t + i * 256;
        int r = s >> 8; int q = s & 255;
        *(float4*)(xs + r * DIM + q * 4) =
            *(const float4*)(x + (size_t)(tok0 + r) * DIM + q * 4);
    }
    __syncthreads();
#pragma unroll
    for (int i = 0; i < 4; i++) {
        int c = (t + i * 256) * 8;
        const float4* sv = (const float4*)(xs + c);
        float4 a = sv[0], b = sv[1];
        __half2 h[4];
        h[0] = __floats2half2_rn(a.x, a.y); h[1] = __floats2half2_rn(a.z, a.w);
        h[2] = __floats2half2_rn(b.x, b.y); h[3] = __floats2half2_rn(b.z, b.w);
        *(uint4*)(g_xh + (size_t)tok0 * DIM + c) = *(uint4*)h;
    }
    int tl = t >> 5, lane = t & 31;
    int tok = tok0 + tl;
    float acc = rb[lane];
    const float4* xv = (const float4*)(xs + tl * DIM);
    const float4* wv = (const float4*)(rw + (size_t)lane * DIM);
#pragma unroll 4
    for (int q = 0; q < DIM / 4; q++) {
        float4 a = xv[q], b = wv[q];
        acc = fmaf(a.x, b.x, acc); acc = fmaf(a.y, b.y, acc);
        acc = fmaf(a.z, b.z, acc); acc = fmaf(a.w, b.w, acc);
    }
    float m = acc;
#pragma unroll
    for (int o = 16; o; o >>= 1) m = fmaxf(m, __shfl_xor_sync(~0u, m, o));
    float p = __expf(acc - m);
    float s = p;
#pragma unroll
    for (int o = 16; o; o >>= 1) s += __shfl_xor_sync(~0u, s, o);
    float sc = p / s;
    float cs[TK]; int ci[TK];
    float cur = sc;
#pragma unroll
    for (int k = 0; k < TK; k++) {
        float v = cur; int vi = lane;
#pragma unroll
        for (int o = 16; o; o >>= 1) {
            float ov = __shfl_xor_sync(~0u, v, o);
            int   oi = __shfl_xor_sync(~0u, vi, o);
            if (ov > v || (ov == v && oi < vi)) { v = ov; vi = oi; }
        }
        cs[k] = v; ci[k] = vi;
        if (lane == vi) cur = -1.f;
    }
    float inv = 1.f / fmaxf(cs[0] + cs[1] + cs[2] + cs[3], 1e-12f);
    if (lane < TK) {
        int e = ci[lane];
        int pos = atomicAdd(&g_cursor[e], 1);
        g_bucket_src[(size_t)e * CAP + pos] = tok * TK + lane;
        g_bucket_sc [(size_t)e * CAP + pos] = cs[lane] * inv;
    }
}

// ---------------- K2: FUSED gate+up+SiLU(+down for routed) --------------------
__global__ __launch_bounds__(512) void gu_all_kernel(
    const __half* __restrict__ gwp, const __half* __restrict__ uwp,
    const __half* __restrict__ sgwp, const __half* __restrict__ suwp,
    const __half* __restrict__ dwp) {
    int by = blockIdx.y;
    int tile0 = blockIdx.x * 128;
    int t = threadIdx.x;
    extern __shared__ __half smh[];
    uint32_t sA = s2u(smh), sBg = sA + 3 * TILE_BYTES, sBu = sA + 6 * TILE_BYTES;
    __shared__ int srcs[128];
    __shared__ float scs[128];

    bool routed = by < NEXP;
    int cnt;
    const __half *Wg, *Wu;
    if (routed) {
        cnt = g_cursor[by];
        if (tile0 >= cnt) return;
        size_t off = (size_t)by * CAP;
        Wg = gwp + (size_t)by * HID * DIM;
        Wu = uwp + (size_t)by * HID * DIM;
        if (t < 128) {
            int m = tile0 + t;
            bool v = m < cnt;
            srcs[t] = v ? g_bucket_src[off + m] : -1;
            scs[t]  = v ? g_bucket_sc[off + m] : 0.f;
        }
    } else {
        int nb = (by - NEXP) * 128;
        cnt = NTOK;
        Wg = sgwp + (size_t)nb * DIM;
        Wu = suwp + (size_t)nb * DIM;
        if (t < 128) srcs[t] = tile0 + t;
    }
    __syncthreads();

    int shift = routed ? 2 : 0;
    int rw_[2], cw[2]; const __half* aP[2]; const __half* gP[2]; const __half* uP[2]; bool av[2];
#pragma unroll
    for (int i = 0; i < 2; i++) {
        int c = t + i * 512; rw_[i] = c >> 3; cw[i] = c & 7;
        int s0 = srcs[rw_[i]];
        av[i] = s0 >= 0;
        int tok = (av[i] ? s0 : 0) >> shift;
        aP[i] = g_xh + (size_t)tok * DIM + cw[i] * 8;
        gP[i] = Wg + (size_t)rw_[i] * DIM + cw[i] * 8;
        uP[i] = Wu + (size_t)rw_[i] * DIM + cw[i] * 8;
    }
    int lane = t & 31, wid = t >> 5;
    int wm = (wid & 3) * 32, wn = (wid >> 2) * 32, g = lane >> 2, tig = lane & 3;
    float accg[2][4][4] = {}, accu[2][4][4] = {};

#define GU_ISSUE(st, kb)                                                        \
    {                                                                           \
        uint32_t so = (uint32_t)(st) * TILE_BYTES;                              \
        _Pragma("unroll")                                                       \
        for (int i = 0; i < 2; i++) {                                           \
            uint32_t o = swz((uint32_t)(rw_[i] * 128 + cw[i] * 16));            \
            cpa16h(sA + so + o, aP[i] + (kb), av[i]);                           \
            cpa16h(sBg + so + o, gP[i] + (kb), true);                           \
            cpa16h(sBu + so + o, uP[i] + (kb), true);                           \
        }                                                                       \
        cp_commit();                                                            \
    }

    const int NIT = DIM / 64;
    GU_ISSUE(0, 0) GU_ISSUE(1, 64)
    for (int it = 0; it < NIT; it++) {
        if (it + 1 < NIT) cp_wait<1>(); else cp_wait<0>();
        __syncthreads();
        int st = it % 3;
        compute_k64h_gu512(sA + st * TILE_BYTES, sBg + st * TILE_BYTES,
                           sBu + st * TILE_BYTES, wm, wn, lane, accg, accu);
        int nx = it + 2;
        if (nx < NIT) GU_ISSUE(nx % 3, nx * 64)
    }
#undef GU_ISSUE

    if (!routed) {
        int nb = (by - NEXP) * 128;
        __half* outp = g_sHh + nb;
#pragma unroll
        for (int mt = 0; mt < 2; mt++) {
            int rA = tile0 + wm + mt * 16 + g;
#pragma unroll
            for (int nt = 0; nt < 4; nt++) {
                int col = wn + nt * 8 + 2 * tig;
                __half2 h0 = __floats2half2_rn(
                    silu_mul(accg[mt][nt][0], accu[mt][nt][0]),
                    silu_mul(accg[mt][nt][1], accu[mt][nt][1]));
                *(__half2*)(outp + (size_t)rA * SHID + col) = h0;
                __half2 h1 = __floats2half2_rn(
                    silu_mul(accg[mt][nt][2], accu[mt][nt][2]),
                    silu_mul(accg[mt][nt][3], accu[mt][nt][3]));
                *(__half2*)(outp + (size_t)(rA + 8) * SHID + col) = h1;
            }
        }
        return;
    }

    __syncthreads();

    const __half* W = dwp + (size_t)by * DIM * HID;
#define WD_ISSUE(j)                                                             \
    {                                                                           \
        int nbv = (j) >> 1, kv = (j) & 1;                                       \
        uint32_t slot = ((uint32_t)(j) % 3) * TILE_BYTES;                       \
        _Pragma("unroll")                                                       \
        for (int i = 0; i < 2; i++) {                                           \
            uint32_t o = swz((uint32_t)(rw_[i] * 128 + cw[i] * 16));            \
            cpa16h(sBg + slot + o,                                              \
                   W + (size_t)(nbv * 128 + rw_[i]) * HID + kv * 64 + cw[i] * 8, true); \
        }                                                                       \
        cp_commit();                                                            \
    }
    WD_ISSUE(0) WD_ISSUE(1)

#pragma unroll
    for (int mt = 0; mt < 2; mt++) {
        int rL = wm + mt * 16 + g;
#pragma unroll
        for (int nt = 0; nt < 4; nt++) {
            int col = wn + nt * 8 + 2 * tig;
            uint32_t chunk = (uint32_t)(col >> 6);
            uint32_t colb = (uint32_t)((col & 63) * 2);
            __half2 h0 = __floats2half2_rn(
                silu_mul(accg[mt][nt][0], accu[mt][nt][0]),
                silu_mul(accg[mt][nt][1], accu[mt][nt][1]));
            sts32(sA + chunk * TILE_BYTES +
                  (((uint32_t)rL * 128 + colb) ^ (((uint32_t)rL & 7) << 4)),
                  *(uint32_t*)&h0);
            int rH = rL + 8;
            __half2 h1 = __floats2half2_rn(
                silu_mul(accg[mt][nt][2], accu[mt][nt][2]),
                silu_mul(accg[mt][nt][3], accu[mt][nt][3]));
            sts32(sA + chunk * TILE_BYTES +
                  (((uint32_t)rH * 128 + colb) ^ (((uint32_t)rH & 7) << 4)),
                  *(uint32_t*)&h1);
        }
    }
    __syncthreads();

    float acc[2][4][4] = {};
    for (int j = 0; j < 16; j++) {
        if (j + 1 < 16) cp_wait<1>(); else cp_wait<0>();
        __syncthreads();
        compute_k64h_32(sA + (j & 1) * TILE_BYTES, sBg + (j % 3) * TILE_BYTES,
                        wm, wn, lane, acc);
        int nx = j + 2;
        if (nx < 16) WD_ISSUE(nx)
        if (j & 1) {
            int nb = j >> 1;
#pragma unroll
            for (int mt = 0; mt < 2; mt++) {
                int rL = wm + mt * 16 + g;
                int s0 = srcs[rL], s1 = srcs[rL + 8];
#pragma unroll
                for (int nt = 0; nt < 4; nt++) {
                    int col = nb * 128 + wn + nt * 8 + 2 * tig;
                    if (s0 >= 0) {
                        float s = scs[rL];
                        *(__half2*)(g_Y + (size_t)s0 * DIM + col) =
                            __floats2half2_rn(acc[mt][nt][0] * s, acc[mt][nt][1] * s);
                    }
                    if (s1 >= 0) {
                        float s = scs[rL + 8];
                        *(__half2*)(g_Y + (size_t)s1 * DIM + col) =
                            __floats2half2_rn(acc[mt][nt][2] * s, acc[mt][nt][3] * s);
                    }
                }
            }
#pragma unroll
            for (int mt = 0; mt < 2; mt++)
#pragma unroll
                for (int nt = 0; nt < 4; nt++)
#pragma unroll
                    for (int v = 0; v < 4; v++) acc[mt][nt][v] = 0.f;
        }
    }
#undef WD_ISSUE
}

// ---------------- K3: final GEMM 128x128 (256 thr, 2 CTA/SM) + Y gather --------
__global__ __launch_bounds__(256, 2) void final_kernel(
    const __half* __restrict__ sdwp, float* __restrict__ out) {
    int tile0 = blockIdx.x * 128;
    int nb = blockIdx.y * 128;
    extern __shared__ __half smh[];
    uint32_t sA = s2u(smh), sB = sA + 3 * TILE_BYTES;
    int t = threadIdx.x;

    int rw_[4], cw[4]; const __half* aP[4]; const __half* bP[4];
#pragma unroll
    for (int i = 0; i < 4; i++) {
        int c = t + i * 256; rw_[i] = c >> 3; cw[i] = c & 7;
        aP[i] = g_sHh + (size_t)(tile0 + rw_[i]) * SHID + cw[i] * 8;
        bP[i] = sdwp + (size_t)(nb + rw_[i]) * SHID + cw[i] * 8;
    }
    int lane = t & 31, wid = t >> 5;
    int wm = (wid & 3) * 32, wn = (wid >> 2) * 64, g = lane >> 2, tig = lane & 3;
    float acc[2][8][4] = {};

#define AB_ISSUE(st, kb)                                                        \
    {                                                                           \
        uint32_t so = (uint32_t)(st) * TILE_BYTES;                              \
        _Pragma("unroll")                                                       \
        for (int i = 0; i < 4; i++) {                                           \
            uint32_t o = swz((uint32_t)(rw_[i] * 128 + cw[i] * 16));            \
            cpa16h(sA + so + o, aP[i] + (kb), true);                            \
            cpa16h(sB + so + o, bP[i] + (kb), true);                            \
        }                                                                       \
        cp_commit();                                                            \
    }

    {
        const int NIT = SHID / 64;
        AB_ISSUE(0, 0) AB_ISSUE(1, 64)
        for (int it = 0; it < NIT; it++) {
            if (it + 1 < NIT) cp_wait<1>(); else cp_wait<0>();
            __syncthreads();
            int st = it % 3;
            compute_k64h(sA + st * TILE_BYTES, sB + st * TILE_BYTES, wm, wn, lane, acc);
            int nx = it + 2;
            if (nx < NIT) AB_ISSUE(nx % 3, nx * 64)
        }
    }
#undef AB_ISSUE

#pragma unroll
    for (int mt = 0; mt < 2; mt++) {
        int r0 = tile0 + wm + mt * 16 + g;
        const __half* ya = g_Y + (size_t)r0 * TK * DIM;
        const __half* yb = g_Y + (size_t)(r0 + 8) * TK * DIM;
#pragma unroll
        for (int nt = 0; nt < 8; nt++) {
            int col = nb + wn + nt * 8 + 2 * tig;
            float2 f0 = __half22float2(*(const __half2*)(ya + col));
            float2 f1 = __half22float2(*(const __half2*)(ya + DIM + col));
            float2 f2 = __half22float2(*(const __half2*)(ya + 2 * DIM + col));
            float2 f3 = __half22float2(*(const __half2*)(ya + 3 * DIM + col));
            float2 ra;
            ra.x = acc[mt][nt][0] + f0.x + f1.x + f2.x + f3.x;
            ra.y = acc[mt][nt][1] + f0.y + f1.y + f2.y + f3.y;
            *(float2*)(out + (size_t)r0 * DIM + col) = ra;
            float2 z0 = __half22float2(*(const __half2*)(yb + col));
            float2 z1 = __half22float2(*(const __half2*)(yb + DIM + col));
            float2 z2 = __half22float2(*(const __half2*)(yb + 2 * DIM + col));
            float2 z3 = __half22float2(*(const __half2*)(yb + 3 * DIM + col));
            float2 rb;
            rb.x = acc[mt][nt][2] + z0.x + z1.x + z2.x + z3.x;
            rb.y = acc[mt][nt][3] + z0.y + z1.y + z2.y + z3.y;
            *(float2*)(out + (size_t)(r0 + 8) * DIM + col) = rb;
        }
    }
}

// ---------------- launch ---------------------------------------------------------
extern "C" void kernel_launch(void* const* d_in, const int* in_sizes, int n_in,
                              void* d_out, int out_size) {
    const float* x   = (const float*)d_in[0];
    const float* rw  = (const float*)d_in[1];
    const float* rb  = (const float*)d_in[2];
    const float* gw  = (const float*)d_in[3];
    const float* uw  = (const float*)d_in[4];
    const float* dw  = (const float*)d_in[5];
    const float* sgw = (const float*)d_in[6];
    const float* suw = (const float*)d_in[7];
    const float* sdw = (const float*)d_in[8];
    float* out = (float*)d_out;

    static __half *p_gwh = nullptr, *p_uwh, *p_dwh, *p_sgwh, *p_suwh, *p_sdwh;
    if (!p_gwh) {
        cudaGetSymbolAddress((void**)&p_gwh,  g_gwh);
        cudaGetSymbolAddress((void**)&p_uwh,  g_uwh);
        cudaGetSymbolAddress((void**)&p_dwh,  g_dwh);
        cudaGetSymbolAddress((void**)&p_sgwh, g_sgwh);
        cudaGetSymbolAddress((void**)&p_suwh, g_suwh);
        cudaGetSymbolAddress((void**)&p_sdwh, g_sdwh);
    }

    cudaFuncSetAttribute(gu_all_kernel, cudaFuncAttributeMaxDynamicSharedMemorySize, SMEM_GU3);
    cudaFuncSetAttribute(final_kernel,  cudaFuncAttributeMaxDynamicSharedMemorySize, SMEM_FIN);

    convw_kernel<<<(W6 / 4 + 255) / 256, 256>>>(gw, uw, dw, sgw, suw, sdw);
    router_scatter_kernel<<<NTOK / 8, 256>>>(x, rw, rb);
    gu_all_kernel<<<dim3(64, NEXP + 4), 512, SMEM_GU3>>>(p_gwh, p_uwh, p_sgwh, p_suwh, p_dwh);
    final_kernel<<<dim3(64, 8), 256, SMEM_FIN>>>(p_sdwh, out);
}

// round 17
// speedup vs baseline: 1.1049x; 1.0106x over previous
#include <cuda_runtime.h>
#include <cuda_fp16.h>
#include <math.h>
#include <stdint.h>

#define NTOK 8192
#define DIM  1024
#define NEXP 32
#define HID  128
#define TK   4
#define SHID 512
#define NROWS (NTOK*TK)
#define CAP  32768

// ---------------- scratch (device globals; no allocations) ----------------
__device__ __align__(16) int   g_cursor[NEXP];
__device__ __align__(16) int   g_bucket_src[(size_t)NEXP * CAP];
__device__ __align__(16) float g_bucket_sc [(size_t)NEXP * CAP];
__device__ __align__(16) __half g_xh[(size_t)NTOK * DIM];
__device__ __align__(16) __half g_gwh[(size_t)NEXP * HID * DIM];
__device__ __align__(16) __half g_uwh[(size_t)NEXP * HID * DIM];
__device__ __align__(16) __half g_dwh[(size_t)NEXP * DIM * HID];
__device__ __align__(16) __half g_sgwh[(size_t)SHID * DIM];
__device__ __align__(16) __half g_suwh[(size_t)SHID * DIM];
__device__ __align__(16) __half g_sdwh[(size_t)DIM * SHID];
__device__ __align__(16) __half g_sHh[(size_t)NTOK * SHID];
__device__ __align__(16) __half g_Y[(size_t)NROWS * DIM];

// ---------------- helpers ---------------------------------------------------
__device__ __forceinline__ uint32_t s2u(const void* p) {
    uint32_t r;
    asm("{.reg .u64 t; cvta.to.shared.u64 t, %1; cvt.u32.u64 %0, t;}" : "=r"(r) : "l"(p));
    return r;
}
__device__ __forceinline__ uint32_t swz(uint32_t b) { return b ^ ((b >> 3) & 0x70); }

__device__ __forceinline__ void cpa16h(uint32_t daddr, const __half* src, bool pred) {
    int sz = pred ? 16 : 0;
    asm volatile("cp.async.cg.shared.global [%0], [%1], 16, %2;\n"
                 :: "r"(daddr), "l"(src), "r"(sz));
}
__device__ __forceinline__ void cp_commit() {
    asm volatile("cp.async.commit_group;\n" ::);
}
template<int N> __device__ __forceinline__ void cp_wait() {
    asm volatile("cp.async.wait_group %0;\n" :: "n"(N));
}
__device__ __forceinline__ void sts32(uint32_t addr, uint32_t v) {
    asm volatile("st.shared.b32 [%0], %1;" :: "r"(addr), "r"(v) : "memory");
}
__device__ __forceinline__ void mma16(float* c, const uint32_t* a, const uint32_t* b) {
    asm volatile(
        "mma.sync.aligned.m16n8k16.row.col.f32.f16.f16.f32 "
        "{%0,%1,%2,%3}, {%4,%5,%6,%7}, {%8,%9}, {%0,%1,%2,%3};"
        : "+f"(c[0]), "+f"(c[1]), "+f"(c[2]), "+f"(c[3])
        : "r"(a[0]), "r"(a[1]), "r"(a[2]), "r"(a[3]), "r"(b[0]), "r"(b[1]));
}
__device__ __forceinline__ float silu_mul(float g, float u) {
    return g / (1.f + __expf(-g)) * u;
}
__device__ __forceinline__ void ldsm4(uint32_t* r, uint32_t addr) {
    asm volatile("ldmatrix.sync.aligned.m8n8.x4.shared.b16 {%0,%1,%2,%3}, [%4];"
        : "=r"(r[0]), "=r"(r[1]), "=r"(r[2]), "=r"(r[3]) : "r"(addr));
}

#define TILE_BYTES 16384u
#define SMEM_GU3  (3 * 3 * TILE_BYTES)
#define SMEM_FIN  (3 * 2 * TILE_BYTES)

// single-B k64 compute, warp tile 32x64
__device__ __forceinline__ void compute_k64h(
    uint32_t sAt, uint32_t sBt, int wm, int wn, int lane, float acc[2][8][4]) {
    int ar = lane & 15, ac = lane >> 4;
    int br = (lane & 7) + ((lane >> 4) & 1) * 8;
    int bc = (lane >> 3) & 1;
#pragma unroll
    for (int ks = 0; ks < 4; ks++) {
        uint32_t af[2][4];
#pragma unroll
        for (int mt = 0; mt < 2; mt++)
            ldsm4(af[mt], sAt + swz((uint32_t)((wm + mt * 16 + ar) * 128 + (ks * 2 + ac) * 16)));
        uint32_t bf[8][2];
#pragma unroll
        for (int j = 0; j < 4; j++) {
            uint32_t r[4];
            ldsm4(r, sBt + swz((uint32_t)((wn + 16 * j + br) * 128 + (ks * 2 + bc) * 16)));
            bf[2*j][0] = r[0]; bf[2*j][1] = r[1]; bf[2*j+1][0] = r[2]; bf[2*j+1][1] = r[3];
        }
#pragma unroll
        for (int mt = 0; mt < 2; mt++)
#pragma unroll
            for (int nt = 0; nt < 8; nt++) mma16(acc[mt][nt], af[mt], bf[nt]);
    }
}

// single-B k64 compute, warp tile 32x32 (down phase)
__device__ __forceinline__ void compute_k64h_32(
    uint32_t sAt, uint32_t sBt, int wm, int wn, int lane, float acc[2][4][4]) {
    int ar = lane & 15, ac = lane >> 4;
    int br = (lane & 7) + ((lane >> 4) & 1) * 8;
    int bc = (lane >> 3) & 1;
#pragma unroll
    for (int ks = 0; ks < 4; ks++) {
        uint32_t af[2][4];
#pragma unroll
        for (int mt = 0; mt < 2; mt++)
            ldsm4(af[mt], sAt + swz((uint32_t)((wm + mt * 16 + ar) * 128 + (ks * 2 + ac) * 16)));
        uint32_t bf[4][2];
#pragma unroll
        for (int j = 0; j < 2; j++) {
            uint32_t r[4];
            ldsm4(r, sBt + swz((uint32_t)((wn + 16 * j + br) * 128 + (ks * 2 + bc) * 16)));
            bf[2*j][0] = r[0]; bf[2*j][1] = r[1]; bf[2*j+1][0] = r[2]; bf[2*j+1][1] = r[3];
        }
#pragma unroll
        for (int mt = 0; mt < 2; mt++)
#pragma unroll
            for (int nt = 0; nt < 4; nt++) mma16(acc[mt][nt], af[mt], bf[nt]);
    }
}

// fused gate+up compute, 512 threads
__device__ __forceinline__ void compute_k64h_gu512(
    uint32_t sAt, uint32_t sBg, uint32_t sBu, int wm, int wn, int lane,
    float accg[2][4][4], float accu[2][4][4]) {
    int ar = lane & 15, ac = lane >> 4;
    int br = (lane & 7) + ((lane >> 4) & 1) * 8;
    int bc = (lane >> 3) & 1;
#pragma unroll
    for (int ks = 0; ks < 4; ks++) {
        uint32_t af[2][4];
#pragma unroll
        for (int mt = 0; mt < 2; mt++)
            ldsm4(af[mt], sAt + swz((uint32_t)((wm + mt * 16 + ar) * 128 + (ks * 2 + ac) * 16)));
        uint32_t bf[4][2];
#pragma unroll
        for (int j = 0; j < 2; j++) {
            uint32_t r[4];
            ldsm4(r, sBg + swz((uint32_t)((wn + 16 * j + br) * 128 + (ks * 2 + bc) * 16)));
            bf[2*j][0] = r[0]; bf[2*j][1] = r[1]; bf[2*j+1][0] = r[2]; bf[2*j+1][1] = r[3];
        }
#pragma unroll
        for (int mt = 0; mt < 2; mt++)
#pragma unroll
            for (int nt = 0; nt < 4; nt++) mma16(accg[mt][nt], af[mt], bf[nt]);
#pragma unroll
        for (int j = 0; j < 2; j++) {
            uint32_t r[4];
            ldsm4(r, sBu + swz((uint32_t)((wn + 16 * j + br) * 128 + (ks * 2 + bc) * 16)));
            bf[2*j][0] = r[0]; bf[2*j][1] = r[1]; bf[2*j+1][0] = r[2]; bf[2*j+1][1] = r[3];
        }
#pragma unroll
        for (int mt = 0; mt < 2; mt++)
#pragma unroll
            for (int nt = 0; nt < 4; nt++) mma16(accu[mt][nt], af[mt], bf[nt]);
    }
}

// ---------------- K0: init cursors ---------------------------------------------
__global__ void init_kernel() {
    if (threadIdx.x < NEXP) g_cursor[threadIdx.x] = 0;
}

// ---------------- K1: merged convW + router/scatter/x->fp16 --------------------
#define NG8  ((unsigned)(NEXP * HID * DIM / 8))
#define NS8  ((unsigned)(SHID * DIM / 8))
#define W1 (NG8)
#define W2 (2u * NG8)
#define W3 (3u * NG8)
#define W4 (W3 + NS8)
#define W5 (W4 + NS8)
#define W6 (W5 + NS8)
#define NCONVB ((W6 / 4 + 255) / 256)      // 1728
#define NROUTB (NTOK / 8)                  // 1024

__global__ __launch_bounds__(256) void pre_kernel(
    const float* __restrict__ x, const float* __restrict__ rw,
    const float* __restrict__ rb,
    const float* __restrict__ gw, const float* __restrict__ uw,
    const float* __restrict__ dw, const float* __restrict__ sgw,
    const float* __restrict__ suw, const float* __restrict__ sdw) {
    __shared__ float xs[8 * DIM];
    int t = threadIdx.x;

    if (blockIdx.x < NCONVB) {
        // ---- weight conversion (32 floats/thread) ----
        unsigned q = (blockIdx.x * 256 + t) * 4;
        if (q >= W6) return;
        const float* src; __half* dst; unsigned base;
        if      (q < W1) { src = gw;  dst = g_gwh;  base = 0; }
        else if (q < W2) { src = uw;  dst = g_uwh;  base = W1; }
        else if (q < W3) { src = dw;  dst = g_dwh;  base = W2; }
        else if (q < W4) { src = sgw; dst = g_sgwh; base = W3; }
        else if (q < W5) { src = suw; dst = g_suwh; base = W4; }
        else             { src = sdw; dst = g_sdwh; base = W5; }
        size_t e = (size_t)(q - base) * 8;
        const float4* s = (const float4*)(src + e);
        float4 v[8];
#pragma unroll
        for (int i = 0; i < 8; i++) v[i] = s[i];
#pragma unroll
        for (int i = 0; i < 4; i++) {
            __half2 h[4];
            h[0] = __floats2half2_rn(v[2*i].x, v[2*i].y);
            h[1] = __floats2half2_rn(v[2*i].z, v[2*i].w);
            h[2] = __floats2half2_rn(v[2*i+1].x, v[2*i+1].y);
            h[3] = __floats2half2_rn(v[2*i+1].z, v[2*i+1].w);
            *(uint4*)(dst + e + i * 8) = *(uint4*)h;
        }
        return;
    }

    // ---- router + softmax + top4 + scatter + x->fp16 (8 tokens/block) ----
    int tok0 = (blockIdx.x - NCONVB) * 8;
#pragma unroll
    for (int i = 0; i < 8; i++) {
        int s = t + i * 256;
        int r = s >> 8; int q = s & 255;
        *(float4*)(xs + r * DIM + q * 4) =
            *(const float4*)(x + (size_t)(tok0 + r) * DIM + q * 4);
    }
    __syncthreads();
#pragma unroll
    for (int i = 0; i < 4; i++) {
        int c = (t + i * 256) * 8;
        const float4* sv = (const float4*)(xs + c);
        float4 a = sv[0], b = sv[1];
        __half2 h[4];
        h[0] = __floats2half2_rn(a.x, a.y); h[1] = __floats2half2_rn(a.z, a.w);
        h[2] = __floats2half2_rn(b.x, b.y); h[3] = __floats2half2_rn(b.z, b.w);
        *(uint4*)(g_xh + (size_t)tok0 * DIM + c) = *(uint4*)h;
    }
    int tl = t >> 5, lane = t & 31;
    int tok = tok0 + tl;
    float acc = rb[lane];
    const float4* xv = (const float4*)(xs + tl * DIM);
    const float4* wv = (const float4*)(rw + (size_t)lane * DIM);
#pragma unroll 4
    for (int q = 0; q < DIM / 4; q++) {
        float4 a = xv[q], b = wv[q];
        acc = fmaf(a.x, b.x, acc); acc = fmaf(a.y, b.y, acc);
        acc = fmaf(a.z, b.z, acc); acc = fmaf(a.w, b.w, acc);
    }
    float m = acc;
#pragma unroll
    for (int o = 16; o; o >>= 1) m = fmaxf(m, __shfl_xor_sync(~0u, m, o));
    float p = __expf(acc - m);
    float s = p;
#pragma unroll
    for (int o = 16; o; o >>= 1) s += __shfl_xor_sync(~0u, s, o);
    float sc = p / s;
    float cs[TK]; int ci[TK];
    float cur = sc;
#pragma unroll
    for (int k = 0; k < TK; k++) {
        float v = cur; int vi = lane;
#pragma unroll
        for (int o = 16; o; o >>= 1) {
            float ov = __shfl_xor_sync(~0u, v, o);
            int   oi = __shfl_xor_sync(~0u, vi, o);
            if (ov > v || (ov == v && oi < vi)) { v = ov; vi = oi; }
        }
        cs[k] = v; ci[k] = vi;
        if (lane == vi) cur = -1.f;
    }
    float inv = 1.f / fmaxf(cs[0] + cs[1] + cs[2] + cs[3], 1e-12f);
    if (lane < TK) {
        int e = ci[lane];
        int pos = atomicAdd(&g_cursor[e], 1);
        g_bucket_src[(size_t)e * CAP + pos] = tok * TK + lane;
        g_bucket_sc [(size_t)e * CAP + pos] = cs[lane] * inv;
    }
}

// ---------------- K2: FUSED gate+up+SiLU(+down for routed) --------------------
__global__ __launch_bounds__(512) void gu_all_kernel(
    const __half* __restrict__ gwp, const __half* __restrict__ uwp,
    const __half* __restrict__ sgwp, const __half* __restrict__ suwp,
    const __half* __restrict__ dwp) {
    int by = blockIdx.y;
    int tile0 = blockIdx.x * 128;
    int t = threadIdx.x;
    extern __shared__ __half smh[];
    uint32_t sA = s2u(smh), sBg = sA + 3 * TILE_BYTES, sBu = sA + 6 * TILE_BYTES;
    __shared__ int srcs[128];
    __shared__ float scs[128];

    bool routed = by < NEXP;
    int cnt;
    const __half *Wg, *Wu;
    if (routed) {
        cnt = g_cursor[by];
        if (tile0 >= cnt) return;
        size_t off = (size_t)by * CAP;
        Wg = gwp + (size_t)by * HID * DIM;
        Wu = uwp + (size_t)by * HID * DIM;
        if (t < 128) {
            int m = tile0 + t;
            bool v = m < cnt;
            srcs[t] = v ? g_bucket_src[off + m] : -1;
            scs[t]  = v ? g_bucket_sc[off + m] : 0.f;
        }
    } else {
        int nb = (by - NEXP) * 128;
        cnt = NTOK;
        Wg = sgwp + (size_t)nb * DIM;
        Wu = suwp + (size_t)nb * DIM;
        if (t < 128) srcs[t] = tile0 + t;
    }
    __syncthreads();

    int shift = routed ? 2 : 0;
    int rw_[2], cw[2]; const __half* aP[2]; const __half* gP[2]; const __half* uP[2]; bool av[2];
#pragma unroll
    for (int i = 0; i < 2; i++) {
        int c = t + i * 512; rw_[i] = c >> 3; cw[i] = c & 7;
        int s0 = srcs[rw_[i]];
        av[i] = s0 >= 0;
        int tok = (av[i] ? s0 : 0) >> shift;
        aP[i] = g_xh + (size_t)tok * DIM + cw[i] * 8;
        gP[i] = Wg + (size_t)rw_[i] * DIM + cw[i] * 8;
        uP[i] = Wu + (size_t)rw_[i] * DIM + cw[i] * 8;
    }
    int lane = t & 31, wid = t >> 5;
    int wm = (wid & 3) * 32, wn = (wid >> 2) * 32, g = lane >> 2, tig = lane & 3;
    float accg[2][4][4] = {}, accu[2][4][4] = {};

#define GU_ISSUE(st, kb)                                                        \
    {                                                                           \
        uint32_t so = (uint32_t)(st) * TILE_BYTES;                              \
        _Pragma("unroll")                                                       \
        for (int i = 0; i < 2; i++) {                                           \
            uint32_t o = swz((uint32_t)(rw_[i] * 128 + cw[i] * 16));            \
            cpa16h(sA + so + o, aP[i] + (kb), av[i]);                           \
            cpa16h(sBg + so + o, gP[i] + (kb), true);                           \
            cpa16h(sBu + so + o, uP[i] + (kb), true);                           \
        }                                                                       \
        cp_commit();                                                            \
    }

    const int NIT = DIM / 64;
    GU_ISSUE(0, 0) GU_ISSUE(1, 64)
    for (int it = 0; it < NIT; it++) {
        if (it + 1 < NIT) cp_wait<1>(); else cp_wait<0>();
        __syncthreads();
        int st = it % 3;
        compute_k64h_gu512(sA + st * TILE_BYTES, sBg + st * TILE_BYTES,
                           sBu + st * TILE_BYTES, wm, wn, lane, accg, accu);
        int nx = it + 2;
        if (nx < NIT) GU_ISSUE(nx % 3, nx * 64)
    }
#undef GU_ISSUE

    if (!routed) {
        int nb = (by - NEXP) * 128;
        __half* outp = g_sHh + nb;
#pragma unroll
        for (int mt = 0; mt < 2; mt++) {
            int rA = tile0 + wm + mt * 16 + g;
#pragma unroll
            for (int nt = 0; nt < 4; nt++) {
                int col = wn + nt * 8 + 2 * tig;
                __half2 h0 = __floats2half2_rn(
                    silu_mul(accg[mt][nt][0], accu[mt][nt][0]),
                    silu_mul(accg[mt][nt][1], accu[mt][nt][1]));
                *(__half2*)(outp + (size_t)rA * SHID + col) = h0;
                __half2 h1 = __floats2half2_rn(
                    silu_mul(accg[mt][nt][2], accu[mt][nt][2]),
                    silu_mul(accg[mt][nt][3], accu[mt][nt][3]));
                *(__half2*)(outp + (size_t)(rA + 8) * SHID + col) = h1;
            }
        }
        return;
    }

    __syncthreads();

    const __half* W = dwp + (size_t)by * DIM * HID;
#define WD_ISSUE(j)                                                             \
    {                                                                           \
        int nbv = (j) >> 1, kv = (j) & 1;                                       \
        uint32_t slot = ((uint32_t)(j) % 3) * TILE_BYTES;                       \
        _Pragma("unroll")                                                       \
        for (int i = 0; i < 2; i++) {                                           \
            uint32_t o = swz((uint32_t)(rw_[i] * 128 + cw[i] * 16));            \
            cpa16h(sBg + slot + o,                                              \
                   W + (size_t)(nbv * 128 + rw_[i]) * HID + kv * 64 + cw[i] * 8, true); \
        }                                                                       \
        cp_commit();                                                            \
    }
    WD_ISSUE(0) WD_ISSUE(1)

#pragma unroll
    for (int mt = 0; mt < 2; mt++) {
        int rL = wm + mt * 16 + g;
#pragma unroll
        for (int nt = 0; nt < 4; nt++) {
            int col = wn + nt * 8 + 2 * tig;
            uint32_t chunk = (uint32_t)(col >> 6);
            uint32_t colb = (uint32_t)((col & 63) * 2);
            __half2 h0 = __floats2half2_rn(
                silu_mul(accg[mt][nt][0], accu[mt][nt][0]),
                silu_mul(accg[mt][nt][1], accu[mt][nt][1]));
            sts32(sA + chunk * TILE_BYTES +
                  (((uint32_t)rL * 128 + colb) ^ (((uint32_t)rL & 7) << 4)),
                  *(uint32_t*)&h0);
            int rH = rL + 8;
            __half2 h1 = __floats2half2_rn(
                silu_mul(accg[mt][nt][2], accu[mt][nt][2]),
                silu_mul(accg[mt][nt][3], accu[mt][nt][3]));
            sts32(sA + chunk * TILE_BYTES +
                  (((uint32_t)rH * 128 + colb) ^ (((uint32_t)rH & 7) << 4)),
                  *(uint32_t*)&h1);
        }
    }
    __syncthreads();

    float acc[2][4][4] = {};
    for (int j = 0; j < 16; j++) {
        if (j + 1 < 16) cp_wait<1>(); else cp_wait<0>();
        __syncthreads();
        compute_k64h_32(sA + (j & 1) * TILE_BYTES, sBg + (j % 3) * TILE_BYTES,
                        wm, wn, lane, acc);
        int nx = j + 2;
        if (nx < 16) WD_ISSUE(nx)
        if (j & 1) {
            int nb = j >> 1;
#pragma unroll
            for (int mt = 0; mt < 2; mt++) {
                int rL = wm + mt * 16 + g;
                int s0 = srcs[rL], s1 = srcs[rL + 8];
#pragma unroll
                for (int nt = 0; nt < 4; nt++) {
                    int col = nb * 128 + wn + nt * 8 + 2 * tig;
                    if (s0 >= 0) {
                        float s = scs[rL];
                        *(__half2*)(g_Y + (size_t)s0 * DIM + col) =
                            __floats2half2_rn(acc[mt][nt][0] * s, acc[mt][nt][1] * s);
                    }
                    if (s1 >= 0) {
                        float s = scs[rL + 8];
                        *(__half2*)(g_Y + (size_t)s1 * DIM + col) =
                            __floats2half2_rn(acc[mt][nt][2] * s, acc[mt][nt][3] * s);
                    }
                }
            }
#pragma unroll
            for (int mt = 0; mt < 2; mt++)
#pragma unroll
                for (int nt = 0; nt < 4; nt++)
#pragma unroll
                    for (int v = 0; v < 4; v++) acc[mt][nt][v] = 0.f;
        }
    }
#undef WD_ISSUE
}

// ---------------- K3: final GEMM + coalesced Y-gather epilogue -----------------
__global__ __launch_bounds__(256, 2) void final_kernel(
    const __half* __restrict__ sdwp, float* __restrict__ out) {
    int tile0 = blockIdx.x * 128;
    int nb = blockIdx.y * 128;
    extern __shared__ __half smh[];
    uint32_t sA = s2u(smh), sB = sA + 3 * TILE_BYTES;
    int t = threadIdx.x;

    int rw_[4], cw[4]; const __half* aP[4]; const __half* bP[4];
#pragma unroll
    for (int i = 0; i < 4; i++) {
        int c = t + i * 256; rw_[i] = c >> 3; cw[i] = c & 7;
        aP[i] = g_sHh + (size_t)(tile0 + rw_[i]) * SHID + cw[i] * 8;
        bP[i] = sdwp + (size_t)(nb + rw_[i]) * SHID + cw[i] * 8;
    }
    int lane = t & 31, wid = t >> 5;
    int wm = (wid & 3) * 32, wn = (wid >> 2) * 64, g = lane >> 2, tig = lane & 3;
    float acc[2][8][4] = {};

#define AB_ISSUE(st, kb)                                                        \
    {                                                                           \
        uint32_t so = (uint32_t)(st) * TILE_BYTES;                              \
        _Pragma("unroll")                                                       \
        for (int i = 0; i < 4; i++) {                                           \
            uint32_t o = swz((uint32_t)(rw_[i] * 128 + cw[i] * 16));            \
            cpa16h(sA + so + o, aP[i] + (kb), true);                            \
            cpa16h(sB + so + o, bP[i] + (kb), true);                            \
        }                                                                       \
        cp_commit();                                                            \
    }

    {
        const int NIT = SHID / 64;
        AB_ISSUE(0, 0) AB_ISSUE(1, 64)
        for (int it = 0; it < NIT; it++) {
            if (it + 1 < NIT) cp_wait<1>(); else cp_wait<0>();
            __syncthreads();
            int st = it % 3;
            compute_k64h(sA + st * TILE_BYTES, sB + st * TILE_BYTES, wm, wn, lane, acc);
            int nx = it + 2;
            if (nx < NIT) AB_ISSUE(nx % 3, nx * 64)
        }
    }
#undef AB_ISSUE

    // stage C tile into smem (fp32, stride 132), then coalesced epilogue
    __syncthreads();                       // all warps done reading pipeline smem
    float* Cs = (float*)smh;               // 128 x 132 fp32 = 67.6 KB < 96 KB
#pragma unroll
    for (int mt = 0; mt < 2; mt++) {
        int row = wm + mt * 16 + g;
#pragma unroll
        for (int nt = 0; nt < 8; nt++) {
            int col = wn + nt * 8 + 2 * tig;
            Cs[row * 132 + col]     = acc[mt][nt][0];
            Cs[row * 132 + col + 1] = acc[mt][nt][1];
            Cs[(row + 8) * 132 + col]     = acc[mt][nt][2];
            Cs[(row + 8) * 132 + col + 1] = acc[mt][nt][3];
        }
    }
    __syncthreads();

    // 2048 chunk-tasks: (row, 8-col chunk). 16 consecutive threads cover one row.
#pragma unroll
    for (int i = 0; i < 8; i++) {
        int id = t + i * 256;
        int row = id >> 4, ch = id & 15;
        int c = ch * 8;
        int r0 = tile0 + row;
        const __half* y = g_Y + (size_t)r0 * TK * DIM + nb + c;
        float o[8];
#pragma unroll
        for (int j = 0; j < 8; j++) o[j] = Cs[row * 132 + c + j];
#pragma unroll
        for (int k = 0; k < TK; k++) {
            uint4 yv = *(const uint4*)(y + (size_t)k * DIM);
            __half2* hp = (__half2*)&yv;
#pragma unroll
            for (int j = 0; j < 4; j++) {
                float2 f = __half22float2(hp[j]);
                o[2*j]     += f.x;
                o[2*j + 1] += f.y;
            }
        }
        float* op = out + (size_t)r0 * DIM + nb + c;
        *(float4*)op       = make_float4(o[0], o[1], o[2], o[3]);
        *(float4*)(op + 4) = make_float4(o[4], o[5], o[6], o[7]);
    }
}

// ---------------- launch ---------------------------------------------------------
extern "C" void kernel_launch(void* const* d_in, const int* in_sizes, int n_in,
                              void* d_out, int out_size) {
    const float* x   = (const float*)d_in[0];
    const float* rw  = (const float*)d_in[1];
    const float* rb  = (const float*)d_in[2];
    const float* gw  = (const float*)d_in[3];
    const float* uw  = (const float*)d_in[4];
    const float* dw  = (const float*)d_in[5];
    const float* sgw = (const float*)d_in[6];
    const float* suw = (const float*)d_in[7];
    const float* sdw = (const float*)d_in[8];
    float* out = (float*)d_out;

    static __half *p_gwh = nullptr, *p_uwh, *p_dwh, *p_sgwh, *p_suwh, *p_sdwh;
    if (!p_gwh) {
        cudaGetSymbolAddress((void**)&p_gwh,  g_gwh);
        cudaGetSymbolAddress((void**)&p_uwh,  g_uwh);
        cudaGetSymbolAddress((void**)&p_dwh,  g_dwh);
        cudaGetSymbolAddress((void**)&p_sgwh, g_sgwh);
        cudaGetSymbolAddress((void**)&p_suwh, g_suwh);
        cudaGetSymbolAddress((void**)&p_sdwh, g_sdwh);
    }

    cudaFuncSetAttribute(gu_all_kernel, cudaFuncAttributeMaxDynamicSharedMemorySize, SMEM_GU3);
    cudaFuncSetAttribute(final_kernel,  cudaFuncAttributeMaxDynamicSharedMemorySize, SMEM_FIN);

    init_kernel<<<1, 32>>>();
    pre_kernel<<<NCONVB + NROUTB, 256>>>(x, rw, rb, gw, uw, dw, sgw, suw, sdw);
    gu_all_kernel<<<dim3(64, NEXP + 4), 512, SMEM_GU3>>>(p_gwh, p_uwh, p_sgwh, p_suwh, p_dwh);
    final_kernel<<<dim3(64, 8), 256, SMEM_FIN>>>(p_sdwh, out);
}